// round 7
// baseline (speedup 1.0000x reference)
#include <cuda_runtime.h>
#include <cstdint>

#define BATCH   262144
#define IN_DIM  768
#define OUT_DIM 32
#define QDEPTH  6
#define UNITS   (BATCH / 8)      // 32768 work units of 8 samples (one per warp)
#define NF4     (IN_DIM / 4)     // 192 float4 per row

// dynamic smem layout:
//   [0,3072)    swv: transposed W1 (floats), 4 x 192 float4
//   [3072,3328) sM ; [3328,3456) sW2 ; [3456,3488) sb2 ; [3488,3492) sb1
//   byte 14016: mbars (4 warps x 2 x 8B)
//   byte 16384: tiles, per warp 2 stages x 4 rows x 3KB (24KB/warp)
#define SMEM_BYTES (16384 + 4 * 24576)   // 112KB -> 2 blocks/SM
#define CHUNK_BYTES 12288                // 4 rows x 3KB

__device__ unsigned g_ctr = 0;           // dynamic work-unit counter

__global__ void reset_kernel() { if (threadIdx.x == 0) g_ctr = 0; }

__device__ __forceinline__ uint32_t s2u(const void* p) {
    uint32_t a;
    asm("{ .reg .u64 t; cvta.to.shared.u64 t, %1; cvt.u32.u64 %0, t; }"
        : "=r"(a) : "l"(p));
    return a;
}
__device__ __forceinline__ void mbar_init(uint32_t m, uint32_t c) {
    asm volatile("mbarrier.init.shared.b64 [%0], %1;" :: "r"(m), "r"(c) : "memory");
}
__device__ __forceinline__ void mbar_expect(uint32_t m, uint32_t b) {
    asm volatile("mbarrier.arrive.expect_tx.shared.b64 _, [%0], %1;"
                 :: "r"(m), "r"(b) : "memory");
}
__device__ __forceinline__ void bulk_g2s(uint32_t dst, const void* src,
                                         uint32_t bytes, uint32_t m) {
    asm volatile(
        "cp.async.bulk.shared::cluster.global.mbarrier::complete_tx::bytes "
        "[%0], [%1], %2, [%3];"
        :: "r"(dst), "l"(src), "r"(bytes), "r"(m) : "memory");
}
__device__ __forceinline__ void mbar_wait(uint32_t m, uint32_t ph) {
    asm volatile(
        "{\n\t.reg .pred P;\n"
        "W%=:\n\tmbarrier.try_wait.parity.acquire.cta.shared::cta.b64 P, [%0], %1;\n"
        "\t@P bra D%=;\n\tbra W%=;\nD%=:\n\t}"
        :: "r"(m), "r"(ph) : "memory");
}

// GEMV over one 4-sample chunk in smem + merge + tanh.
// Returns per-lane angle for acc index bitrev4(lane&15) (dup over bit4).
__device__ __forceinline__ float gemv_chunk(const float4* __restrict__ X,
                                            const float4* __restrict__ swv,
                                            float myb1, int lane) {
    float a[16];
#pragma unroll
    for (int i = 0; i < 16; i++) a[i] = 0.0f;
#pragma unroll
    for (int it = 0; it < 6; it++) {
        const int fx = it * 32 + lane;
        float4 w0 = swv[fx], w1 = swv[192 + fx];
        float4 w2 = swv[384 + fx], w3 = swv[576 + fx];
#pragma unroll
        for (int k = 0; k < 4; k++) {
            float4 x = X[k * 192 + fx];
            a[k*4+0] = fmaf(x.x, w0.x, fmaf(x.y, w0.y, fmaf(x.z, w0.z, fmaf(x.w, w0.w, a[k*4+0]))));
            a[k*4+1] = fmaf(x.x, w1.x, fmaf(x.y, w1.y, fmaf(x.z, w1.z, fmaf(x.w, w1.w, a[k*4+1]))));
            a[k*4+2] = fmaf(x.x, w2.x, fmaf(x.y, w2.y, fmaf(x.z, w2.z, fmaf(x.w, w2.w, a[k*4+2]))));
            a[k*4+3] = fmaf(x.x, w3.x, fmaf(x.y, w3.y, fmaf(x.z, w3.z, fmaf(x.w, w3.w, a[k*4+3]))));
        }
    }
#pragma unroll
    for (int step = 0; step < 4; step++) {
        const int off = 1 << step;
        const int n   = 8 >> step;
        const bool up = (lane & off) != 0;
#pragma unroll
        for (int j = 0; j < n; j++) {
            float keep = up ? a[j + n] : a[j];
            float send = up ? a[j] : a[j + n];
            a[j] = keep + __shfl_xor_sync(0xffffffffu, send, off);
        }
    }
    a[0] += __shfl_xor_sync(0xffffffffu, a[0], 16);
    const float PI4 = 0.78539816339744830962f;
    return tanhf(a[0] + myb1) * PI4 + PI4;
}

__global__ void __launch_bounds__(128) fused_kernel(
    const float* __restrict__ inp,
    const float4* __restrict__ w1v,
    const float* __restrict__ b1,
    const float* __restrict__ qw,
    const float* __restrict__ w2,
    const float* __restrict__ b2,
    float* __restrict__ out)
{
    extern __shared__ float sm[];
    float4* swv = (float4*)sm;
    float*  sM  = sm + 3072;
    float*  sW2 = sm + 3328;
    float*  sb2 = sm + 3456;
    float*  sb1 = sm + 3488;

    const int tid  = threadIdx.x;
    const int lane = tid & 31;
    const int warp = tid >> 5;

    const uint32_t smemU   = s2u(sm);
    const uint32_t mb0     = smemU + 14016 + warp * 16;
    const uint32_t mb1     = mb0 + 8;
    const uint32_t tileU   = smemU + 16384 + warp * 24576;
    const float4*  tilesF4 = (const float4*)sm + 1024 + warp * 1536;

    // ---- per-warp mbar init + first ticket + prologue copies ----
    unsigned tk = 0;
    if (lane == 0) {
        mbar_init(mb0, 1);
        mbar_init(mb1, 1);
        asm volatile("fence.proxy.async.shared::cta;" ::: "memory");
        tk = atomicAdd(&g_ctr, 1u);
    }
    __syncwarp();
    unsigned u = __shfl_sync(0xffffffffu, tk, 0);
    if (lane == 0 && u < UNITS) {
        const float* src = inp + (size_t)u * 8 * IN_DIM;
        mbar_expect(mb0, CHUNK_BYTES);
        bulk_g2s(tileU, src, CHUNK_BYTES, mb0);
        mbar_expect(mb1, CHUNK_BYTES);
        bulk_g2s(tileU + CHUNK_BYTES, src + 4 * IN_DIM, CHUNK_BYTES, mb1);
    }

    // ---- constants: transpose W1, small tables ----
    for (int g = tid; g < NF4; g += 128) {
        float4 a = w1v[4 * g],     b = w1v[4 * g + 1];
        float4 c = w1v[4 * g + 2], d = w1v[4 * g + 3];
        swv[g]       = make_float4(a.x, b.x, c.x, d.x);
        swv[192 + g] = make_float4(a.y, b.y, c.y, d.y);
        swv[384 + g] = make_float4(a.z, b.z, c.z, d.z);
        swv[576 + g] = make_float4(a.w, b.w, c.w, d.w);
    }
    if (tid < 128) sW2[tid] = w2[tid];
    if (tid < 32)  sb2[tid] = b2[tid];
    if (tid < 4)   sb1[tid] = b1[tid];

    // ---- warp 3 lanes 0-15: fixed-circuit matrix M (column j per lane) ----
    if (warp == 3 && lane < 16) {
        const int j = lane;
        float v[16];
#pragma unroll
        for (int i = 0; i < 16; i++) v[i] = (i == j) ? 1.0f : 0.0f;
        const int cmA[3] = {8, 2, 4};
        const int tmA[3] = {4, 1, 2};
        for (int k = 0; k < QDEPTH; k++) {
#pragma unroll
            for (int g = 0; g < 3; g++) {
                int cmask = cmA[g], tmask = tmA[g];
#pragma unroll
                for (int i = 0; i < 16; i++)
                    if ((i & cmask) && !(i & tmask)) {
                        float t = v[i]; v[i] = v[i | tmask]; v[i | tmask] = t;
                    }
            }
#pragma unroll
            for (int w = 0; w < 4; w++) {
                int mask = 8 >> w;
                float s, c;
                __sincosf(0.5f * qw[k * 4 + w], &s, &c);
#pragma unroll
                for (int i = 0; i < 16; i++)
                    if (!(i & mask)) {
                        float a0 = v[i], a1 = v[i | mask];
                        v[i]        = c * a0 - s * a1;
                        v[i | mask] = s * a0 + c * a1;
                    }
            }
        }
#pragma unroll
        for (int i = 0; i < 16; i++) sM[i * 16 + j] = v[i];
    }
    __syncthreads();

    // ---- hoist per-lane constants ----
    const int   midx = __brev(lane & 15) >> 28;
    const float myb1 = sb1[midx & 3];
    const float rw0 = sW2[lane], rw1 = sW2[32 + lane];
    const float rw2 = sW2[64 + lane], rw3 = sW2[96 + lane];
    const float rb2 = sb2[lane];
    const float4* sM4 = (const float4*)sM;

    uint32_t ph0 = 0, ph1 = 0;

    while (u < UNITS) {
        // grab next ticket early (latency hidden under chunk A compute)
        unsigned tkn = 0;
        if (lane == 0) tkn = atomicAdd(&g_ctr, 1u);

        // half 0 (samples 0-3 of unit u)
        mbar_wait(mb0, ph0);  ph0 ^= 1;
        float thA = gemv_chunk(tilesF4, swv, myb1, lane);

        unsigned un = __shfl_sync(0xffffffffu, tkn, 0);
        const float* srcn = inp + (size_t)un * 8 * IN_DIM;
        const bool more = (un < UNITS) && (lane == 0);
        if (more) { mbar_expect(mb0, CHUNK_BYTES); bulk_g2s(tileU, srcn, CHUNK_BYTES, mb0); }

        // half 1 (samples 4-7)
        mbar_wait(mb1, ph1);  ph1 ^= 1;
        float thB = gemv_chunk(tilesF4 + 768, swv, myb1, lane);
        if (more) { mbar_expect(mb1, CHUNK_BYTES); bulk_g2s(tileU + CHUNK_BYTES, srcn + 4 * IN_DIM, CHUNK_BYTES, mb1); }

        // ---- gather 4 angles for sample s = lane&7 ----
        const int s = lane & 7;
        float ang[4];
#pragma unroll
        for (int d = 0; d < 4; d++) {
            const int src = __brev(((s & 3) << 2) | d) >> 28;
            float vA = __shfl_sync(0xffffffffu, thA, src);
            float vB = __shfl_sync(0xffffffffu, thB, src);
            ang[d] = (s >= 4) ? vB : vA;
        }

        // ---- quantum tail (thread-per-sample; lanes 8-31 duplicate) ----
        float s0, c0, s1, c1, s2, c2, s3, c3;
        __sincosf(ang[0], &s0, &c0);
        __sincosf(ang[1], &s1, &c1);
        __sincosf(ang[2], &s2, &c2);
        __sincosf(ang[3], &s3, &c3);
        float A[4]  = {c0 * c1, c0 * s1, s0 * c1, s0 * s1};
        float Bq[4] = {c2 * c3, c2 * s3, s2 * c3, s2 * s3};
        float sv[16];
#pragma unroll
        for (int i = 0; i < 16; i++) sv[i] = A[i >> 2] * Bq[i & 3];

        float q0 = 0.f, q1 = 0.f, q2 = 0.f, q3 = 0.f;
#pragma unroll
        for (int i = 0; i < 16; i++) {
            float4 m0 = sM4[4 * i],     m1 = sM4[4 * i + 1];
            float4 m2 = sM4[4 * i + 2], m3 = sM4[4 * i + 3];
            float tt = m0.x * sv[0]  + m0.y * sv[1]  + m0.z * sv[2]  + m0.w * sv[3]
                     + m1.x * sv[4]  + m1.y * sv[5]  + m1.z * sv[6]  + m1.w * sv[7]
                     + m2.x * sv[8]  + m2.y * sv[9]  + m2.z * sv[10] + m2.w * sv[11]
                     + m3.x * sv[12] + m3.y * sv[13] + m3.z * sv[14] + m3.w * sv[15];
            float p = tt * tt;
            q0 += (i & 8) ? -p : p;
            q1 += (i & 4) ? -p : p;
            q2 += (i & 2) ? -p : p;
            q3 += (i & 1) ? -p : p;
        }

        // ---- output: 8 coalesced 128B rows ----
        float* obase = out + (size_t)u * 8 * OUT_DIM;
#pragma unroll
        for (int k = 0; k < 8; k++) {
            float a0 = __shfl_sync(0xffffffffu, q0, k);
            float a1 = __shfl_sync(0xffffffffu, q1, k);
            float a2 = __shfl_sync(0xffffffffu, q2, k);
            float a3 = __shfl_sync(0xffffffffu, q3, k);
            obase[k * OUT_DIM + lane] =
                rb2 + a0 * rw0 + a1 * rw1 + a2 * rw2 + a3 * rw3;
        }

        u = un;
    }
}

// ---------------------------------------------------------------------------
extern "C" void kernel_launch(void* const* d_in, const int* in_sizes, int n_in,
                              void* d_out, int out_size) {
    const float* inputs = (const float*)d_in[0];
    const float* W1     = (const float*)d_in[1];
    const float* b1     = (const float*)d_in[2];
    const float* qw     = (const float*)d_in[3];
    const float* W2     = (const float*)d_in[4];
    const float* b2     = (const float*)d_in[5];

    int sms = 148;
    cudaDeviceGetAttribute(&sms, cudaDevAttrMultiProcessorCount, 0);
    int grid = 2 * sms;

    cudaFuncSetAttribute(fused_kernel,
                         cudaFuncAttributeMaxDynamicSharedMemorySize, SMEM_BYTES);
    fused_kernel<<<grid, 128, SMEM_BYTES>>>(inputs, (const float4*)W1, b1, qw,
                                            W2, b2, (float*)d_out);
    reset_kernel<<<1, 32>>>();   // counter back to 0 for the next replay
}

// round 8
// speedup vs baseline: 1.0353x; 1.0353x over previous
#include <cuda_runtime.h>
#include <cstdint>

#define BATCH   262144
#define IN_DIM  768
#define OUT_DIM 32
#define QDEPTH  6
#define UNITS   (BATCH / 8)      // 32768 work units of 8 samples (one per warp)
#define NF4     (IN_DIM / 4)     // 192 float4 per row

// dynamic smem layout:
//   [0,3072)    swv: transposed W1 (floats), 4 x 192 float4
//   [3072,3328) sM ; [3328,3456) sW2 ; [3456,3488) sb2 ; [3488,3492) sb1
//   byte 14016: mbars (4 warps x 2 x 8B)
//   byte 16384: tiles, per warp 2 stages x 4 rows x 3KB (24KB/warp)
#define SMEM_BYTES (16384 + 4 * 24576)   // 112KB -> 2 blocks/SM
#define CHUNK_BYTES 12288                // 4 rows x 3KB

__device__ unsigned g_ctr  = 0;          // dynamic work-unit counter
__device__ unsigned g_done = 0;          // finished-block counter (self-reset)

__device__ __forceinline__ uint32_t s2u(const void* p) {
    uint32_t a;
    asm("{ .reg .u64 t; cvta.to.shared.u64 t, %1; cvt.u32.u64 %0, t; }"
        : "=r"(a) : "l"(p));
    return a;
}
__device__ __forceinline__ void mbar_init(uint32_t m, uint32_t c) {
    asm volatile("mbarrier.init.shared.b64 [%0], %1;" :: "r"(m), "r"(c) : "memory");
}
__device__ __forceinline__ void mbar_expect(uint32_t m, uint32_t b) {
    asm volatile("mbarrier.arrive.expect_tx.shared.b64 _, [%0], %1;"
                 :: "r"(m), "r"(b) : "memory");
}
__device__ __forceinline__ void bulk_g2s(uint32_t dst, const void* src,
                                         uint32_t bytes, uint32_t m) {
    asm volatile(
        "cp.async.bulk.shared::cluster.global.mbarrier::complete_tx::bytes "
        "[%0], [%1], %2, [%3];"
        :: "r"(dst), "l"(src), "r"(bytes), "r"(m) : "memory");
}
__device__ __forceinline__ void mbar_wait(uint32_t m, uint32_t ph) {
    asm volatile(
        "{\n\t.reg .pred P;\n"
        "W%=:\n\tmbarrier.try_wait.parity.acquire.cta.shared::cta.b64 P, [%0], %1;\n"
        "\t@P bra D%=;\n\tbra W%=;\nD%=:\n\t}"
        :: "r"(m), "r"(ph) : "memory");
}

// GEMV over one 4-sample chunk in smem + merge + tanh.
// Returns per-lane angle for acc index bitrev4(lane&15) (dup over bit4).
__device__ __forceinline__ float gemv_chunk(const float4* __restrict__ X,
                                            const float4* __restrict__ swv,
                                            float myb1, int lane) {
    float a[16];
#pragma unroll
    for (int i = 0; i < 16; i++) a[i] = 0.0f;
#pragma unroll
    for (int it = 0; it < 6; it++) {
        const int fx = it * 32 + lane;
        float4 w0 = swv[fx], w1 = swv[192 + fx];
        float4 w2 = swv[384 + fx], w3 = swv[576 + fx];
#pragma unroll
        for (int k = 0; k < 4; k++) {
            float4 x = X[k * 192 + fx];
            a[k*4+0] = fmaf(x.x, w0.x, fmaf(x.y, w0.y, fmaf(x.z, w0.z, fmaf(x.w, w0.w, a[k*4+0]))));
            a[k*4+1] = fmaf(x.x, w1.x, fmaf(x.y, w1.y, fmaf(x.z, w1.z, fmaf(x.w, w1.w, a[k*4+1]))));
            a[k*4+2] = fmaf(x.x, w2.x, fmaf(x.y, w2.y, fmaf(x.z, w2.z, fmaf(x.w, w2.w, a[k*4+2]))));
            a[k*4+3] = fmaf(x.x, w3.x, fmaf(x.y, w3.y, fmaf(x.z, w3.z, fmaf(x.w, w3.w, a[k*4+3]))));
        }
    }
#pragma unroll
    for (int step = 0; step < 4; step++) {
        const int off = 1 << step;
        const int n   = 8 >> step;
        const bool up = (lane & off) != 0;
#pragma unroll
        for (int j = 0; j < n; j++) {
            float keep = up ? a[j + n] : a[j];
            float send = up ? a[j] : a[j + n];
            a[j] = keep + __shfl_xor_sync(0xffffffffu, send, off);
        }
    }
    a[0] += __shfl_xor_sync(0xffffffffu, a[0], 16);
    const float PI4 = 0.78539816339744830962f;
    return tanhf(a[0] + myb1) * PI4 + PI4;
}

__global__ void __launch_bounds__(128) fused_kernel(
    const float* __restrict__ inp,
    const float4* __restrict__ w1v,
    const float* __restrict__ b1,
    const float* __restrict__ qw,
    const float* __restrict__ w2,
    const float* __restrict__ b2,
    float* __restrict__ out)
{
    extern __shared__ float sm[];
    float4* swv = (float4*)sm;
    float*  sM  = sm + 3072;
    float*  sW2 = sm + 3328;
    float*  sb2 = sm + 3456;
    float*  sb1 = sm + 3488;

    const int tid  = threadIdx.x;
    const int lane = tid & 31;
    const int warp = tid >> 5;

    const uint32_t smemU   = s2u(sm);
    const uint32_t mb0     = smemU + 14016 + warp * 16;
    const uint32_t mb1     = mb0 + 8;
    const uint32_t tileU   = smemU + 16384 + warp * 24576;
    const float4*  tilesF4 = (const float4*)sm + 1024 + warp * 1536;

    // ---- per-warp mbar init + first ticket + prologue copies ----
    unsigned tk = 0;
    if (lane == 0) {
        mbar_init(mb0, 1);
        mbar_init(mb1, 1);
        asm volatile("fence.proxy.async.shared::cta;" ::: "memory");
        tk = atomicAdd(&g_ctr, 1u);
    }
    __syncwarp();
    unsigned u = __shfl_sync(0xffffffffu, tk, 0);
    if (lane == 0 && u < UNITS) {
        const float* src = inp + (size_t)u * 8 * IN_DIM;
        mbar_expect(mb0, CHUNK_BYTES);
        bulk_g2s(tileU, src, CHUNK_BYTES, mb0);
        mbar_expect(mb1, CHUNK_BYTES);
        bulk_g2s(tileU + CHUNK_BYTES, src + 4 * IN_DIM, CHUNK_BYTES, mb1);
    }

    // ---- constants: transpose W1, small tables ----
    for (int g = tid; g < NF4; g += 128) {
        float4 a = w1v[4 * g],     b = w1v[4 * g + 1];
        float4 c = w1v[4 * g + 2], d = w1v[4 * g + 3];
        swv[g]       = make_float4(a.x, b.x, c.x, d.x);
        swv[192 + g] = make_float4(a.y, b.y, c.y, d.y);
        swv[384 + g] = make_float4(a.z, b.z, c.z, d.z);
        swv[576 + g] = make_float4(a.w, b.w, c.w, d.w);
    }
    if (tid < 128) sW2[tid] = w2[tid];
    if (tid < 32)  sb2[tid] = b2[tid];
    if (tid < 4)   sb1[tid] = b1[tid];

    // ---- warp 3 lanes 0-15: fixed-circuit matrix M (column j per lane) ----
    if (warp == 3 && lane < 16) {
        const int j = lane;
        float v[16];
#pragma unroll
        for (int i = 0; i < 16; i++) v[i] = (i == j) ? 1.0f : 0.0f;
        const int cmA[3] = {8, 2, 4};
        const int tmA[3] = {4, 1, 2};
        for (int k = 0; k < QDEPTH; k++) {
#pragma unroll
            for (int g = 0; g < 3; g++) {
                int cmask = cmA[g], tmask = tmA[g];
#pragma unroll
                for (int i = 0; i < 16; i++)
                    if ((i & cmask) && !(i & tmask)) {
                        float t = v[i]; v[i] = v[i | tmask]; v[i | tmask] = t;
                    }
            }
#pragma unroll
            for (int w = 0; w < 4; w++) {
                int mask = 8 >> w;
                float s, c;
                __sincosf(0.5f * qw[k * 4 + w], &s, &c);
#pragma unroll
                for (int i = 0; i < 16; i++)
                    if (!(i & mask)) {
                        float a0 = v[i], a1 = v[i | mask];
                        v[i]        = c * a0 - s * a1;
                        v[i | mask] = s * a0 + c * a1;
                    }
            }
        }
#pragma unroll
        for (int i = 0; i < 16; i++) sM[i * 16 + j] = v[i];
    }
    __syncthreads();

    // ---- hoist per-lane constants ----
    const int   midx = __brev(lane & 15) >> 28;
    const float myb1 = sb1[midx & 3];
    const float rw0 = sW2[lane], rw1 = sW2[32 + lane];
    const float rw2 = sW2[64 + lane], rw3 = sW2[96 + lane];
    const float rb2 = sb2[lane];
    const float4* sM4 = (const float4*)sM;

    uint32_t ph0 = 0, ph1 = 0;

    while (u < UNITS) {
        // grab next ticket early (latency hidden under chunk A compute)
        unsigned tkn = 0;
        if (lane == 0) tkn = atomicAdd(&g_ctr, 1u);

        // half 0 (samples 0-3 of unit u)
        mbar_wait(mb0, ph0);  ph0 ^= 1;
        float thA = gemv_chunk(tilesF4, swv, myb1, lane);

        unsigned un = __shfl_sync(0xffffffffu, tkn, 0);
        const float* srcn = inp + (size_t)un * 8 * IN_DIM;
        const bool more = (un < UNITS) && (lane == 0);
        if (more) { mbar_expect(mb0, CHUNK_BYTES); bulk_g2s(tileU, srcn, CHUNK_BYTES, mb0); }

        // half 1 (samples 4-7)
        mbar_wait(mb1, ph1);  ph1 ^= 1;
        float thB = gemv_chunk(tilesF4 + 768, swv, myb1, lane);
        if (more) { mbar_expect(mb1, CHUNK_BYTES); bulk_g2s(tileU + CHUNK_BYTES, srcn + 4 * IN_DIM, CHUNK_BYTES, mb1); }

        // ---- gather 4 angles for sample s = lane&7 ----
        const int s = lane & 7;
        float ang[4];
#pragma unroll
        for (int d = 0; d < 4; d++) {
            const int src = __brev(((s & 3) << 2) | d) >> 28;
            float vA = __shfl_sync(0xffffffffu, thA, src);
            float vB = __shfl_sync(0xffffffffu, thB, src);
            ang[d] = (s >= 4) ? vB : vA;
        }

        // ---- quantum tail (thread-per-sample; lanes 8-31 duplicate) ----
        float s0, c0, s1, c1, s2, c2, s3, c3;
        __sincosf(ang[0], &s0, &c0);
        __sincosf(ang[1], &s1, &c1);
        __sincosf(ang[2], &s2, &c2);
        __sincosf(ang[3], &s3, &c3);
        float A[4]  = {c0 * c1, c0 * s1, s0 * c1, s0 * s1};
        float Bq[4] = {c2 * c3, c2 * s3, s2 * c3, s2 * s3};
        float sv[16];
#pragma unroll
        for (int i = 0; i < 16; i++) sv[i] = A[i >> 2] * Bq[i & 3];

        float q0 = 0.f, q1 = 0.f, q2 = 0.f, q3 = 0.f;
#pragma unroll
        for (int i = 0; i < 16; i++) {
            float4 m0 = sM4[4 * i],     m1 = sM4[4 * i + 1];
            float4 m2 = sM4[4 * i + 2], m3 = sM4[4 * i + 3];
            float tt = m0.x * sv[0]  + m0.y * sv[1]  + m0.z * sv[2]  + m0.w * sv[3]
                     + m1.x * sv[4]  + m1.y * sv[5]  + m1.z * sv[6]  + m1.w * sv[7]
                     + m2.x * sv[8]  + m2.y * sv[9]  + m2.z * sv[10] + m2.w * sv[11]
                     + m3.x * sv[12] + m3.y * sv[13] + m3.z * sv[14] + m3.w * sv[15];
            float p = tt * tt;
            q0 += (i & 8) ? -p : p;
            q1 += (i & 4) ? -p : p;
            q2 += (i & 2) ? -p : p;
            q3 += (i & 1) ? -p : p;
        }

        // ---- output: 8 coalesced 128B rows ----
        float* obase = out + (size_t)u * 8 * OUT_DIM;
#pragma unroll
        for (int k = 0; k < 8; k++) {
            float a0 = __shfl_sync(0xffffffffu, q0, k);
            float a1 = __shfl_sync(0xffffffffu, q1, k);
            float a2 = __shfl_sync(0xffffffffu, q2, k);
            float a3 = __shfl_sync(0xffffffffu, q3, k);
            obase[k * OUT_DIM + lane] =
                rb2 + a0 * rw0 + a1 * rw1 + a2 * rw2 + a3 * rw3;
        }

        u = un;
    }

    // ---- self-reset: last block to finish zeroes the counters ----
    // Every warp in this block is past its final g_ctr access here.
    __syncthreads();
    if (tid == 0) {
        __threadfence();
        unsigned prev = atomicAdd(&g_done, 1u);
        if (prev == gridDim.x - 1) {     // all other blocks fully done
            g_ctr  = 0;
            g_done = 0;
            __threadfence();
        }
    }
}

// ---------------------------------------------------------------------------
extern "C" void kernel_launch(void* const* d_in, const int* in_sizes, int n_in,
                              void* d_out, int out_size) {
    const float* inputs = (const float*)d_in[0];
    const float* W1     = (const float*)d_in[1];
    const float* b1     = (const float*)d_in[2];
    const float* qw     = (const float*)d_in[3];
    const float* W2     = (const float*)d_in[4];
    const float* b2     = (const float*)d_in[5];

    int sms = 148;
    cudaDeviceGetAttribute(&sms, cudaDevAttrMultiProcessorCount, 0);
    int grid = 2 * sms;

    cudaFuncSetAttribute(fused_kernel,
                         cudaFuncAttributeMaxDynamicSharedMemorySize, SMEM_BYTES);
    fused_kernel<<<grid, 128, SMEM_BYTES>>>(inputs, (const float4*)W1, b1, qw,
                                            W2, b2, (float*)d_out);
}

// round 9
// speedup vs baseline: 1.0496x; 1.0138x over previous
#include <cuda_runtime.h>
#include <cstdint>

#define BATCH   262144
#define IN_DIM  768
#define OUT_DIM 32
#define QDEPTH  6
#define UNITS   (BATCH / 8)      // 32768 work units of 8 samples (one per warp)
#define NF4     (IN_DIM / 4)     // 192 float4 per row

// dynamic smem layout:
//   [0,3072)    swv: transposed W1 (floats), 4 x 192 float4
//   [3072,3328) sM ; [3328,3456) sW2 ; [3456,3488) sb2 ; [3488,3492) sb1
//   byte 14016: mbars (4 warps x 2 x 8B)
//   byte 16384: tiles, per warp 2 stages x 4 rows x 3KB (24KB/warp)
#define SMEM_BYTES (16384 + 4 * 24576)   // 112KB -> 2 blocks/SM
#define CHUNK_BYTES 12288                // 4 rows x 3KB

__device__ unsigned g_ctr  = 0;          // dynamic work-unit counter
__device__ unsigned g_done = 0;          // finished-block counter (self-reset)

__device__ __forceinline__ uint32_t s2u(const void* p) {
    uint32_t a;
    asm("{ .reg .u64 t; cvta.to.shared.u64 t, %1; cvt.u32.u64 %0, t; }"
        : "=r"(a) : "l"(p));
    return a;
}
__device__ __forceinline__ void mbar_init(uint32_t m, uint32_t c) {
    asm volatile("mbarrier.init.shared.b64 [%0], %1;" :: "r"(m), "r"(c) : "memory");
}
__device__ __forceinline__ void mbar_expect(uint32_t m, uint32_t b) {
    asm volatile("mbarrier.arrive.expect_tx.shared.b64 _, [%0], %1;"
                 :: "r"(m), "r"(b) : "memory");
}
// bulk copy with L2 evict-first policy (input is stream-once)
__device__ __forceinline__ void bulk_g2s(uint32_t dst, const void* src,
                                         uint32_t bytes, uint32_t m) {
    asm volatile(
        "{\n\t.reg .b64 pol;\n"
        "\tcreatepolicy.fractional.L2::evict_first.b64 pol, 1.0;\n"
        "\tcp.async.bulk.shared::cluster.global.mbarrier::complete_tx::bytes"
        ".L2::cache_hint [%0], [%1], %2, [%3], pol;\n\t}"
        :: "r"(dst), "l"(src), "r"(bytes), "r"(m) : "memory");
}
__device__ __forceinline__ void mbar_wait(uint32_t m, uint32_t ph) {
    asm volatile(
        "{\n\t.reg .pred P;\n"
        "W%=:\n\tmbarrier.try_wait.parity.acquire.cta.shared::cta.b64 P, [%0], %1;\n"
        "\t@P bra D%=;\n\tbra W%=;\nD%=:\n\t}"
        :: "r"(m), "r"(ph) : "memory");
}
__device__ __forceinline__ void stcs(float* p, float v) {
    asm volatile("st.global.cs.f32 [%0], %1;" :: "l"(p), "f"(v) : "memory");
}

// GEMV over one 4-sample chunk in smem + merge + tanh.
// Returns per-lane angle for acc index bitrev4(lane&15) (dup over bit4).
__device__ __forceinline__ float gemv_chunk(const float4* __restrict__ X,
                                            const float4* __restrict__ swv,
                                            float myb1, int lane) {
    float a[16];
#pragma unroll
    for (int i = 0; i < 16; i++) a[i] = 0.0f;
#pragma unroll
    for (int it = 0; it < 6; it++) {
        const int fx = it * 32 + lane;
        float4 w0 = swv[fx], w1 = swv[192 + fx];
        float4 w2 = swv[384 + fx], w3 = swv[576 + fx];
#pragma unroll
        for (int k = 0; k < 4; k++) {
            float4 x = X[k * 192 + fx];
            a[k*4+0] = fmaf(x.x, w0.x, fmaf(x.y, w0.y, fmaf(x.z, w0.z, fmaf(x.w, w0.w, a[k*4+0]))));
            a[k*4+1] = fmaf(x.x, w1.x, fmaf(x.y, w1.y, fmaf(x.z, w1.z, fmaf(x.w, w1.w, a[k*4+1]))));
            a[k*4+2] = fmaf(x.x, w2.x, fmaf(x.y, w2.y, fmaf(x.z, w2.z, fmaf(x.w, w2.w, a[k*4+2]))));
            a[k*4+3] = fmaf(x.x, w3.x, fmaf(x.y, w3.y, fmaf(x.z, w3.z, fmaf(x.w, w3.w, a[k*4+3]))));
        }
    }
#pragma unroll
    for (int step = 0; step < 4; step++) {
        const int off = 1 << step;
        const int n   = 8 >> step;
        const bool up = (lane & off) != 0;
#pragma unroll
        for (int j = 0; j < n; j++) {
            float keep = up ? a[j + n] : a[j];
            float send = up ? a[j] : a[j + n];
            a[j] = keep + __shfl_xor_sync(0xffffffffu, send, off);
        }
    }
    a[0] += __shfl_xor_sync(0xffffffffu, a[0], 16);
    const float PI4 = 0.78539816339744830962f;
    return tanhf(a[0] + myb1) * PI4 + PI4;
}

__global__ void __launch_bounds__(128) fused_kernel(
    const float* __restrict__ inp,
    const float4* __restrict__ w1v,
    const float* __restrict__ b1,
    const float* __restrict__ qw,
    const float* __restrict__ w2,
    const float* __restrict__ b2,
    float* __restrict__ out)
{
    extern __shared__ float sm[];
    float4* swv = (float4*)sm;
    float*  sM  = sm + 3072;
    float*  sW2 = sm + 3328;
    float*  sb2 = sm + 3456;
    float*  sb1 = sm + 3488;

    const int tid  = threadIdx.x;
    const int lane = tid & 31;
    const int warp = tid >> 5;

    const uint32_t smemU   = s2u(sm);
    const uint32_t mb0     = smemU + 14016 + warp * 16;
    const uint32_t mb1     = mb0 + 8;
    const uint32_t tileU   = smemU + 16384 + warp * 24576;
    const float4*  tilesF4 = (const float4*)sm + 1024 + warp * 1536;

    // ---- per-warp mbar init + first ticket + prologue copies ----
    unsigned tk = 0;
    if (lane == 0) {
        mbar_init(mb0, 1);
        mbar_init(mb1, 1);
        asm volatile("fence.proxy.async.shared::cta;" ::: "memory");
        tk = atomicAdd(&g_ctr, 1u);
    }
    __syncwarp();
    unsigned u = __shfl_sync(0xffffffffu, tk, 0);
    if (lane == 0 && u < UNITS) {
        const float* src = inp + (size_t)u * 8 * IN_DIM;
        mbar_expect(mb0, CHUNK_BYTES);
        bulk_g2s(tileU, src, CHUNK_BYTES, mb0);
        mbar_expect(mb1, CHUNK_BYTES);
        bulk_g2s(tileU + CHUNK_BYTES, src + 4 * IN_DIM, CHUNK_BYTES, mb1);
    }

    // ---- constants: transpose W1, small tables ----
    for (int g = tid; g < NF4; g += 128) {
        float4 a = w1v[4 * g],     b = w1v[4 * g + 1];
        float4 c = w1v[4 * g + 2], d = w1v[4 * g + 3];
        swv[g]       = make_float4(a.x, b.x, c.x, d.x);
        swv[192 + g] = make_float4(a.y, b.y, c.y, d.y);
        swv[384 + g] = make_float4(a.z, b.z, c.z, d.z);
        swv[576 + g] = make_float4(a.w, b.w, c.w, d.w);
    }
    if (tid < 128) sW2[tid] = w2[tid];
    if (tid < 32)  sb2[tid] = b2[tid];
    if (tid < 4)   sb1[tid] = b1[tid];

    // ---- warp 3 lanes 0-15: fixed-circuit matrix M (column j per lane) ----
    if (warp == 3 && lane < 16) {
        const int j = lane;
        float v[16];
#pragma unroll
        for (int i = 0; i < 16; i++) v[i] = (i == j) ? 1.0f : 0.0f;
        const int cmA[3] = {8, 2, 4};
        const int tmA[3] = {4, 1, 2};
        for (int k = 0; k < QDEPTH; k++) {
#pragma unroll
            for (int g = 0; g < 3; g++) {
                int cmask = cmA[g], tmask = tmA[g];
#pragma unroll
                for (int i = 0; i < 16; i++)
                    if ((i & cmask) && !(i & tmask)) {
                        float t = v[i]; v[i] = v[i | tmask]; v[i | tmask] = t;
                    }
            }
#pragma unroll
            for (int w = 0; w < 4; w++) {
                int mask = 8 >> w;
                float s, c;
                __sincosf(0.5f * qw[k * 4 + w], &s, &c);
#pragma unroll
                for (int i = 0; i < 16; i++)
                    if (!(i & mask)) {
                        float a0 = v[i], a1 = v[i | mask];
                        v[i]        = c * a0 - s * a1;
                        v[i | mask] = s * a0 + c * a1;
                    }
            }
        }
#pragma unroll
        for (int i = 0; i < 16; i++) sM[i * 16 + j] = v[i];
    }
    __syncthreads();

    // ---- hoist per-lane constants ----
    const int   midx = __brev(lane & 15) >> 28;
    const float myb1 = sb1[midx & 3];
    const float rw0 = sW2[lane], rw1 = sW2[32 + lane];
    const float rw2 = sW2[64 + lane], rw3 = sW2[96 + lane];
    const float rb2 = sb2[lane];
    const float4* sM4 = (const float4*)sM;

    uint32_t ph0 = 0, ph1 = 0;

    while (u < UNITS) {
        // grab next ticket early (latency hidden under chunk A compute)
        unsigned tkn = 0;
        if (lane == 0) tkn = atomicAdd(&g_ctr, 1u);

        // half 0 (samples 0-3 of unit u)
        mbar_wait(mb0, ph0);  ph0 ^= 1;
        float thA = gemv_chunk(tilesF4, swv, myb1, lane);

        unsigned un = __shfl_sync(0xffffffffu, tkn, 0);
        const float* srcn = inp + (size_t)un * 8 * IN_DIM;
        const bool more = (un < UNITS) && (lane == 0);
        if (more) { mbar_expect(mb0, CHUNK_BYTES); bulk_g2s(tileU, srcn, CHUNK_BYTES, mb0); }

        // half 1 (samples 4-7)
        mbar_wait(mb1, ph1);  ph1 ^= 1;
        float thB = gemv_chunk(tilesF4 + 768, swv, myb1, lane);
        if (more) { mbar_expect(mb1, CHUNK_BYTES); bulk_g2s(tileU + CHUNK_BYTES, srcn + 4 * IN_DIM, CHUNK_BYTES, mb1); }

        // ---- gather 4 angles for sample s = lane&7 ----
        const int s = lane & 7;
        float ang[4];
#pragma unroll
        for (int d = 0; d < 4; d++) {
            const int src = __brev(((s & 3) << 2) | d) >> 28;
            float vA = __shfl_sync(0xffffffffu, thA, src);
            float vB = __shfl_sync(0xffffffffu, thB, src);
            ang[d] = (s >= 4) ? vB : vA;
        }

        // ---- quantum tail (thread-per-sample; lanes 8-31 duplicate) ----
        float s0, c0, s1, c1, s2, c2, s3, c3;
        __sincosf(ang[0], &s0, &c0);
        __sincosf(ang[1], &s1, &c1);
        __sincosf(ang[2], &s2, &c2);
        __sincosf(ang[3], &s3, &c3);
        float A[4]  = {c0 * c1, c0 * s1, s0 * c1, s0 * s1};
        float Bq[4] = {c2 * c3, c2 * s3, s2 * c3, s2 * s3};
        float sv[16];
#pragma unroll
        for (int i = 0; i < 16; i++) sv[i] = A[i >> 2] * Bq[i & 3];

        float q0 = 0.f, q1 = 0.f, q2 = 0.f, q3 = 0.f;
#pragma unroll
        for (int i = 0; i < 16; i++) {
            float4 m0 = sM4[4 * i],     m1 = sM4[4 * i + 1];
            float4 m2 = sM4[4 * i + 2], m3 = sM4[4 * i + 3];
            float tt = m0.x * sv[0]  + m0.y * sv[1]  + m0.z * sv[2]  + m0.w * sv[3]
                     + m1.x * sv[4]  + m1.y * sv[5]  + m1.z * sv[6]  + m1.w * sv[7]
                     + m2.x * sv[8]  + m2.y * sv[9]  + m2.z * sv[10] + m2.w * sv[11]
                     + m3.x * sv[12] + m3.y * sv[13] + m3.z * sv[14] + m3.w * sv[15];
            float p = tt * tt;
            q0 += (i & 8) ? -p : p;
            q1 += (i & 4) ? -p : p;
            q2 += (i & 2) ? -p : p;
            q3 += (i & 1) ? -p : p;
        }

        // ---- output: 8 coalesced 128B rows, streaming stores ----
        float* obase = out + (size_t)u * 8 * OUT_DIM;
#pragma unroll
        for (int k = 0; k < 8; k++) {
            float a0 = __shfl_sync(0xffffffffu, q0, k);
            float a1 = __shfl_sync(0xffffffffu, q1, k);
            float a2 = __shfl_sync(0xffffffffu, q2, k);
            float a3 = __shfl_sync(0xffffffffu, q3, k);
            stcs(obase + k * OUT_DIM + lane,
                 rb2 + a0 * rw0 + a1 * rw1 + a2 * rw2 + a3 * rw3);
        }

        u = un;
    }

    // ---- self-reset: last block to finish zeroes the counters ----
    __syncthreads();
    if (tid == 0) {
        __threadfence();
        unsigned prev = atomicAdd(&g_done, 1u);
        if (prev == gridDim.x - 1) {     // all other blocks fully done
            g_ctr  = 0;
            g_done = 0;
            __threadfence();
        }
    }
}

// ---------------------------------------------------------------------------
extern "C" void kernel_launch(void* const* d_in, const int* in_sizes, int n_in,
                              void* d_out, int out_size) {
    const float* inputs = (const float*)d_in[0];
    const float* W1     = (const float*)d_in[1];
    const float* b1     = (const float*)d_in[2];
    const float* qw     = (const float*)d_in[3];
    const float* W2     = (const float*)d_in[4];
    const float* b2     = (const float*)d_in[5];

    int sms = 148;
    cudaDeviceGetAttribute(&sms, cudaDevAttrMultiProcessorCount, 0);
    int grid = 2 * sms;

    cudaFuncSetAttribute(fused_kernel,
                         cudaFuncAttributeMaxDynamicSharedMemorySize, SMEM_BYTES);
    fused_kernel<<<grid, 128, SMEM_BYTES>>>(inputs, (const float4*)W1, b1, qw,
                                            W2, b2, (float*)d_out);
}